// round 17
// baseline (speedup 1.0000x reference)
#include <cuda_runtime.h>
#include <cuda_fp16.h>
#include <cstdint>

#define BATCH 16
#define CH    128
#define HGT   128
#define WID   128
#define NTHR  256

#define NSTAGE 12              // 3 kh * 4 ci-chunks (32 ci each)
#define B_ROW_W     272        // words per input row within a ci4 group
#define B_CI4_STRIDE 552       // words per ci4 group; 552%32==8 -> conflict-free LDS.64
#define SLOT_W (8*B_CI4_STRIDE)          // 4416 words = 17664 B (B only)
#define SMEM_DYN (4*SLOT_W*4)            // 70656 B -> 2 CTAs/SM (epilogue eb 66560B fits)
#define EP_STRIDE 260

__device__ float    g_x  [(size_t)BATCH*CH*HGT*WID];     // fp32 state
__device__ uint32_t g_xh [(size_t)BATCH*32*HGT*WID*2];   // [b][ci4][h][w][2] half2 words
__device__ uint32_t g_th [(size_t)BATCH*32*HGT*WID*2];
__device__ uint32_t g_wph[2*2*12*3072];                  // packed fp16 weights

// ---------- helpers ----------
__device__ __forceinline__ uint32_t smem_u32(const void* p){
    uint32_t a; asm("{ .reg .u64 t; cvta.to.shared.u64 t, %1; cvt.u32.u64 %0, t; }":"=r"(a):"l"(p));
    return a;
}
__device__ __forceinline__ void cp16(uint32_t dst, const void* src, uint32_t ss){
    asm volatile("cp.async.cg.shared.global [%0], [%1], 16, %2;"
                 :: "r"(dst), "l"(src), "r"(ss) : "memory");
}
#define CP_COMMIT() asm volatile("cp.async.commit_group;":::"memory")
template<int N> __device__ __forceinline__ void cp_wait(){
    asm volatile("cp.async.wait_group %0;"::"n"(N):"memory");
}
__device__ __forceinline__ void mma16(float* d, const uint4& a, uint32_t b0, uint32_t b1){
    asm volatile("mma.sync.aligned.m16n8k16.row.col.f32.f16.f16.f32 "
        "{%0,%1,%2,%3}, {%4,%5,%6,%7}, {%8,%9}, {%0,%1,%2,%3};"
        : "+f"(d[0]), "+f"(d[1]), "+f"(d[2]), "+f"(d[3])
        : "r"(a.x), "r"(a.y), "r"(a.z), "r"(a.w), "r"(b0), "r"(b1));
}
// pack two fp32 -> half2 word, low half = lo
__device__ __forceinline__ uint32_t pk2(float lo, float hi){
    uint32_t r;
    asm("cvt.rn.f16x2.f32 %0, %1, %2;" : "=r"(r) : "f"(hi), "f"(lo));
    return r;
}

// ---------- weight pack: fp16 fragment layout, channel-quad k-mapping ----------
__global__ void pack_wh(const float* __restrict__ w1, const float* __restrict__ w2,
                        uint32_t* __restrict__ dst){
    int idx = blockIdx.x*blockDim.x + threadIdx.x;
    if (idx >= 2*73728) return;
    int r = idx;
    int set = r / 73728; r %= 73728;
    int ch  = r / 36864; r %= 36864;
    int s   = r / 3072;  r %= 3072;
    int kw  = r / 1024;  r %= 1024;
    int j   = r / 512;   r %= 512;
    int m16 = r / 128;   r %= 128;
    int lane = r >> 2;
    int rr   = r & 3;
    int g = lane>>2, t = lane&3;
    int co = ch*64 + m16*16 + g + ((rr&1)<<3);
    int kh = s>>2, chunk = s&3;
    int ci = chunk*32 + (j*4 + t)*4 + ((rr>>1)<<1);
    const float* w = set ? w2 : w1;
    float lo = w[((size_t)co*CH + ci  )*9 + kh*3 + kw];
    float hi = w[((size_t)co*CH + ci+1)*9 + kh*3 + kw];
    dst[idx] = pk2(lo, hi);
}

// ---------- convert x -> [b][ci4][h][w][2] half2 words ----------
__global__ void convert_x(const float* __restrict__ in, uint32_t* __restrict__ out){
    const int total = BATCH*32*HGT*(WID/2);
    for (int i = blockIdx.x*blockDim.x + threadIdx.x; i < total; i += gridDim.x*blockDim.x){
        int wp = i & 63; int r = i >> 6;
        int h  = r & 127; r >>= 7;
        int ci4 = r & 31; int b = r >> 5;
        int c0 = 4*ci4, w0 = wp*2;
        const float* p = in + (((size_t)b*CH + c0)*HGT + h)*WID + w0;
        const size_t cs = (size_t)HGT*WID;
        float2 v0 = *(const float2*)(p);
        float2 v1 = *(const float2*)(p + cs);
        float2 v2 = *(const float2*)(p + 2*cs);
        float2 v3 = *(const float2*)(p + 3*cs);
        uint4 o;
        o.x = pk2(v0.x, v1.x); o.y = pk2(v2.x, v3.x);
        o.z = pk2(v0.y, v1.y); o.w = pk2(v2.y, v3.y);
        *(uint4*)(out + ((((size_t)b*32 + ci4)*HGT + h)*WID + w0)*2) = o;
    }
}

// ---------- conv kernel ----------
// MODE 0: t = relu(conv+b)            -> outh only
// MODE 1: v = xadd + (conv+b)/3       -> outf (fp32) + outh
// MODE 2: v = relu(xadd + (conv+b)/3) -> outf only
template<int MODE>
__global__ void __launch_bounds__(NTHR, 2)
conv_mma(const uint32_t* __restrict__ inh, const uint32_t* __restrict__ wph,
         const float* __restrict__ bias, const float* __restrict__ xadd,
         float* __restrict__ outf, uint32_t* __restrict__ outh)
{
    extern __shared__ __align__(1024) float sm[];
    uint32_t* smw = (uint32_t*)sm;
    const int tid = threadIdx.x, lane = tid&31, wid = tid>>5;
    const int g = lane>>2, t = lane&3;
    const int wm = wid&1, wn = wid>>1;
    const int brow = wn>>1, nb = (wn&1)*64;
    const int h0 = blockIdx.x*2, b = blockIdx.y, ch = blockIdx.z;
    const uint32_t* in_b = inh + (size_t)b*32*HGT*WID*2;
    const uint32_t* wpc  = wph + (size_t)ch*36864;

    float d[2][8][4];
#pragma unroll
    for (int mt=0;mt<2;mt++)
#pragma unroll
        for (int nt=0;nt<8;nt++)
#pragma unroll
            for (int c=0;c<4;c++) d[mt][nt][c] = 0.f;

    auto issue_stage = [&](int s, int slot){
        uint32_t* sl = smw + slot*SLOT_W;
        uint32_t base = smem_u32(sl);
        // B: 8 ci4 x 2 rows x 64 chunks (2px*2words) = 1024 cp16
        const int kh = s>>2, chunk = s&3;
#pragma unroll
        for (int i=0;i<4;i++){
            int v = tid + i*256;
            int ci4 = v>>7, rem = v&127, row = rem>>6, cw = rem&63;
            int r = h0 + kh - 1 + row;
            uint32_t ss = ((unsigned)r < HGT) ? 16u : 0u;
            int rc = ((unsigned)r < HGT) ? r : 0;
            const uint32_t* src = in_b + ((((size_t)(chunk*8+ci4))*HGT + rc)*WID + 2*cw)*2;
            cp16(base + (ci4*B_CI4_STRIDE + row*B_ROW_W + 8 + 4*cw)*4, src, ss);
        }
        // halo zeros: words 6,7 (px=-1) and 264,265 (px=128) per row
        if (tid < 64){
            int ci4 = tid>>3, r3 = tid&7;
            int row = r3>>2, q = r3&3;
            int wd = ((q>>1) ? 264 : 6) + (q&1);
            sl[ci4*B_CI4_STRIDE + row*B_ROW_W + wd] = 0;
        }
    };

    issue_stage(0, 0); CP_COMMIT();
    issue_stage(1, 1); CP_COMMIT();
    issue_stage(2, 2); CP_COMMIT();

    int slot = 0;
    for (int s=0; s<NSTAGE; s++){
        if (s <= NSTAGE-3)      cp_wait<2>();
        else if (s == NSTAGE-2) cp_wait<1>();
        else                    cp_wait<0>();
        __syncthreads();

        const uint32_t* Bb = smw + slot*SLOT_W;
        const uint32_t* Ag = wpc + (size_t)s*3072;   // weights: LDG, L1-cached broadcast
#pragma unroll
        for (int j=0; j<2; j++){
            const uint32_t* bt = Bb + (j*4+t)*B_CI4_STRIDE + brow*B_ROW_W + (nb + g + 3)*2;
#pragma unroll
            for (int kw=0; kw<3; kw++){
                uint4 av0 = __ldg((const uint4*)(Ag + ((kw*2+j)*4 + wm*2  )*128 + lane*4));
                uint4 av1 = __ldg((const uint4*)(Ag + ((kw*2+j)*4 + wm*2+1)*128 + lane*4));
#pragma unroll
                for (int nt=0; nt<8; nt++){
                    uint2 bb = *(const uint2*)(bt + (kw + 8*nt)*2);
                    mma16(d[0][nt], av0, bb.x, bb.y);
                    mma16(d[1][nt], av1, bb.x, bb.y);
                }
            }
        }

        if (s < NSTAGE-3){
            int nslot = slot+3; if (nslot >= 4) nslot -= 4;
            issue_stage(s+3, nslot);
            CP_COMMIT();
        }
        slot = (slot+1) & 3;
    }

    // ---- epilogue ----
    __syncthreads();
    float* eb = sm;   // 64co x 256px, stride EP_STRIDE (66560B <= 70656B)
#pragma unroll
    for (int mt=0; mt<2; mt++){
        const int r0 = wm*32 + mt*16 + g;
        const float bv0 = bias[ch*64 + r0];
        const float bv1 = bias[ch*64 + r0 + 8];
        const int a0 = r0*EP_STRIDE + brow*128 + nb + 2*t;
#pragma unroll
        for (int nt=0; nt<8; nt++){
            float v0 = d[mt][nt][0] + bv0, v1 = d[mt][nt][1] + bv0;
            float v2 = d[mt][nt][2] + bv1, v3 = d[mt][nt][3] + bv1;
            if (MODE == 0){
                v0 = fmaxf(v0,0.f); v1 = fmaxf(v1,0.f);
                v2 = fmaxf(v2,0.f); v3 = fmaxf(v3,0.f);
            }
            eb[a0 + nt*8]                  = v0;
            eb[a0 + nt*8 + 1]              = v1;
            eb[a0 + 8*EP_STRIDE + nt*8]    = v2;
            eb[a0 + 8*EP_STRIDE + nt*8 +1] = v3;
        }
    }
    __syncthreads();

    const float inv3 = 1.0f/3.0f;
    if (MODE != 0){
        for (int it = tid; it < 64*64; it += NTHR){
            int co = it>>6, p4 = it&63;
            float4 v = *(const float4*)&eb[co*EP_STRIDE + p4*4];
            int hh = h0 + (p4>>5), w = (p4&31)*4;
            size_t gi = (((size_t)b*CH + ch*64 + co)*HGT + hh)*WID + w;
            float4 xv = *(const float4*)&xadd[gi];
            v.x = xv.x + inv3*v.x; v.y = xv.y + inv3*v.y;
            v.z = xv.z + inv3*v.z; v.w = xv.w + inv3*v.w;
            if (MODE == 2){
                v.x = fmaxf(v.x,0.f); v.y = fmaxf(v.y,0.f);
                v.z = fmaxf(v.z,0.f); v.w = fmaxf(v.w,0.f);
            }
            *(float4*)&outf[gi] = v;
            if (MODE == 1) *(float4*)&eb[co*EP_STRIDE + p4*4] = v;
        }
    }
    if (MODE == 1) __syncthreads();
    if (MODE != 2){
        for (int it = tid; it < 2048; it += NTHR){
            int wp = it & 63; int r = it >> 6;
            int row = r & 1; int q = r >> 1;
            int p = row*128 + wp*2;
            const float* e0 = &eb[(4*q  )*EP_STRIDE + p];
            const float* e1 = &eb[(4*q+1)*EP_STRIDE + p];
            const float* e2 = &eb[(4*q+2)*EP_STRIDE + p];
            const float* e3 = &eb[(4*q+3)*EP_STRIDE + p];
            uint4 o;
            o.x = pk2(e0[0], e1[0]); o.y = pk2(e2[0], e3[0]);
            o.z = pk2(e0[1], e1[1]); o.w = pk2(e2[1], e3[1]);
            *(uint4*)(outh + ((((size_t)b*32 + ch*16 + q)*HGT + (h0+row))*WID + wp*2)*2) = o;
        }
    }
}

// ---------- launch ----------
extern "C" void kernel_launch(void* const* d_in, const int* in_sizes, int n_in,
                              void* d_out, int out_size)
{
    const float* x  = (const float*)d_in[0];
    const float* w1 = (const float*)d_in[1];
    const float* b1 = (const float*)d_in[2];
    const float* w2 = (const float*)d_in[3];
    const float* b2 = (const float*)d_in[4];
    float* out = (float*)d_out;

    float *gx; uint32_t *gxh, *gth, *gwph;
    cudaGetSymbolAddress((void**)&gx,   g_x);
    cudaGetSymbolAddress((void**)&gxh,  g_xh);
    cudaGetSymbolAddress((void**)&gth,  g_th);
    cudaGetSymbolAddress((void**)&gwph, g_wph);

    cudaFuncSetAttribute(conv_mma<0>, cudaFuncAttributeMaxDynamicSharedMemorySize, SMEM_DYN);
    cudaFuncSetAttribute(conv_mma<1>, cudaFuncAttributeMaxDynamicSharedMemorySize, SMEM_DYN);
    cudaFuncSetAttribute(conv_mma<2>, cudaFuncAttributeMaxDynamicSharedMemorySize, SMEM_DYN);

    pack_wh<<<(2*73728 + 255)/256, 256>>>(w1, w2, gwph);
    convert_x<<<4096, 256>>>(x, gxh);

    const uint32_t* wp1 = gwph;
    const uint32_t* wp2 = gwph + 73728;
    dim3 grid(HGT/2, BATCH, 2);

    conv_mma<0><<<grid, NTHR, SMEM_DYN>>>(gxh, wp1, b1, nullptr, nullptr, gth);
    conv_mma<1><<<grid, NTHR, SMEM_DYN>>>(gth, wp2, b2, x,       gx,      gxh);
    conv_mma<0><<<grid, NTHR, SMEM_DYN>>>(gxh, wp1, b1, nullptr, nullptr, gth);
    conv_mma<1><<<grid, NTHR, SMEM_DYN>>>(gth, wp2, b2, gx,      gx,      gxh);
    conv_mma<0><<<grid, NTHR, SMEM_DYN>>>(gxh, wp1, b1, nullptr, nullptr, gth);
    conv_mma<2><<<grid, NTHR, SMEM_DYN>>>(gth, wp2, b2, gx,      out,     nullptr);
}